// round 7
// baseline (speedup 1.0000x reference)
#include <cuda_runtime.h>

#define Bsz 512
#define Tt  128
#define Ff  256
#define Hh  384
#define Ll  3
#define Kw  10
#define LAB 25
#define GATES 1542   // 4*H + 2*L

// ---------------- device scratch ----------------
__device__ float g_xw[(size_t)Bsz * Tt * GATES];    // input-GEMM results
__device__ float g_xop[3][(size_t)Bsz * GATES];     // K-split partials of h@rec_w
__device__ float g_h[Bsz * Hh];
__device__ float g_c[Bsz * Hh];
__device__ float g_hhist[(size_t)Tt * Bsz * Hh];
__device__ float g_dist[Tt * Bsz];

__device__ __forceinline__ float sigf(float x) { return 1.0f / (1.0f + __expf(-x)); }
__device__ __forceinline__ float tanhfast(float x) { return 1.0f - 2.0f / (1.0f + __expf(2.0f * x)); }

__global__ void init_state() {
    for (int i = blockIdx.x * blockDim.x + threadIdx.x; i < Bsz * Hh;
         i += gridDim.x * blockDim.x) {
        g_h[i] = 0.0f; g_c[i] = 0.0f;
    }
}

// ============ gemm_xw: g_xw = [X, t>0] @ kernel_w + kernel_b ============
// M=65536, K=256, N=1542. 128x128 tile, BK=16, 8x8 micro, double-buffered.
__global__ __launch_bounds__(256, 2) void gemm_xw(const float* __restrict__ X,
                                                  const float* __restrict__ kw,
                                                  const float* __restrict__ kbias) {
    __shared__ __align__(16) float As[2][16][128];
    __shared__ __align__(16) float Bs[2][16][128];
    const int bn = blockIdx.x * 128, bm = blockIdx.y * 128;
    const int tid = threadIdx.x;
    const int tm = (tid >> 4) << 3, tn = (tid & 15) << 3;
    const int a_r = tid >> 2, a_k4 = (tid & 3) * 4;
    const int b_k = tid >> 6, b_n = (tid & 63) * 2;

    float4 pa[2]; float2 pb[4];
    float acc[8][8] = {};

    auto ldA = [&](int k0) {
#pragma unroll
        for (int r = 0; r < 2; r++)
            pa[r] = *(const float4*)(X + (size_t)(bm + a_r + 64 * r) * Ff + k0 + a_k4);
    };
    auto ldB = [&](int k0) {
#pragma unroll
        for (int r = 0; r < 4; r++) {
            int n = bn + b_n;
            float2 v = make_float2(0.0f, 0.0f);
            if (n < GATES) v = *(const float2*)(kw + (size_t)(k0 + b_k + 4 * r) * GATES + n);
            pb[r] = v;
        }
    };
    auto stA = [&](int buf) {
#pragma unroll
        for (int r = 0; r < 2; r++) {
            As[buf][a_k4 + 0][a_r + 64 * r] = pa[r].x;
            As[buf][a_k4 + 1][a_r + 64 * r] = pa[r].y;
            As[buf][a_k4 + 2][a_r + 64 * r] = pa[r].z;
            As[buf][a_k4 + 3][a_r + 64 * r] = pa[r].w;
        }
    };
    auto stB = [&](int buf) {
#pragma unroll
        for (int r = 0; r < 4; r++) {
            Bs[buf][b_k + 4 * r][b_n] = pb[r].x;
            Bs[buf][b_k + 4 * r][b_n + 1] = pb[r].y;
        }
    };

    const int NB = Ff / 16;
    ldA(0); ldB(0); stA(0); stB(0);
    __syncthreads();
    for (int kblk = 0; kblk < NB; kblk++) {
        int nxt = kblk + 1;
        if (nxt < NB) { ldA(nxt * 16); ldB(nxt * 16); }
        int p = kblk & 1;
#pragma unroll
        for (int kk = 0; kk < 16; kk++) {
            float4 a0 = *(const float4*)&As[p][kk][tm];
            float4 a1 = *(const float4*)&As[p][kk][tm + 4];
            float4 b0 = *(const float4*)&Bs[p][kk][tn];
            float4 b1 = *(const float4*)&Bs[p][kk][tn + 4];
            float av[8] = {a0.x, a0.y, a0.z, a0.w, a1.x, a1.y, a1.z, a1.w};
            float bv[8] = {b0.x, b0.y, b0.z, b0.w, b1.x, b1.y, b1.z, b1.w};
#pragma unroll
            for (int i = 0; i < 8; i++)
#pragma unroll
                for (int j = 0; j < 8; j++) acc[i][j] += av[i] * bv[j];
        }
        if (nxt < NB) { int q = nxt & 1; stA(q); stB(q); }
        __syncthreads();
    }
#pragma unroll
    for (int i = 0; i < 8; i++) {
        int m = bm + tm + i;
        int t = m & (Tt - 1);
#pragma unroll
        for (int j = 0; j < 8; j++) {
            int n = bn + tn + j;
            if (n < GATES) {
                float v = acc[i][j] + kbias[n];
                if (t > 0) v += kw[(size_t)Ff * GATES + n];
                g_xw[(size_t)m * GATES + n] = v;
            }
        }
    }
}

// ============ gemm_rec: g_xop[ks] = h @ rec_w[ks*128:(ks+1)*128] ============
// M=512, K=128 per split (3 splits), N=1542. 128x128 tile, 8x8 micro.
__global__ __launch_bounds__(256, 2) void gemm_rec(const float* __restrict__ rw) {
    __shared__ __align__(16) float As[2][16][128];
    __shared__ __align__(16) float Bs[2][16][128];
    const int bn = blockIdx.x * 128, bm = blockIdx.y * 128;
    const int ks = blockIdx.z, kbase = ks * 128;
    const int tid = threadIdx.x;
    const int tm = (tid >> 4) << 3, tn = (tid & 15) << 3;
    const int a_r = tid >> 2, a_k4 = (tid & 3) * 4;
    const int b_k = tid >> 6, b_n = (tid & 63) * 2;

    float4 pa[2]; float2 pb[4];
    float acc[8][8] = {};

    auto ldA = [&](int k0) {
#pragma unroll
        for (int r = 0; r < 2; r++)
            pa[r] = *(const float4*)(g_h + (size_t)(bm + a_r + 64 * r) * Hh + k0 + a_k4);
    };
    auto ldB = [&](int k0) {
#pragma unroll
        for (int r = 0; r < 4; r++) {
            int n = bn + b_n;
            float2 v = make_float2(0.0f, 0.0f);
            if (n < GATES) v = *(const float2*)(rw + (size_t)(k0 + b_k + 4 * r) * GATES + n);
            pb[r] = v;
        }
    };
    auto stA = [&](int buf) {
#pragma unroll
        for (int r = 0; r < 2; r++) {
            As[buf][a_k4 + 0][a_r + 64 * r] = pa[r].x;
            As[buf][a_k4 + 1][a_r + 64 * r] = pa[r].y;
            As[buf][a_k4 + 2][a_r + 64 * r] = pa[r].z;
            As[buf][a_k4 + 3][a_r + 64 * r] = pa[r].w;
        }
    };
    auto stB = [&](int buf) {
#pragma unroll
        for (int r = 0; r < 4; r++) {
            Bs[buf][b_k + 4 * r][b_n] = pb[r].x;
            Bs[buf][b_k + 4 * r][b_n + 1] = pb[r].y;
        }
    };

    const int NB = 128 / 16;
    ldA(kbase); ldB(kbase); stA(0); stB(0);
    __syncthreads();
    for (int kblk = 0; kblk < NB; kblk++) {
        int nxt = kblk + 1;
        if (nxt < NB) { ldA(kbase + nxt * 16); ldB(kbase + nxt * 16); }
        int p = kblk & 1;
#pragma unroll
        for (int kk = 0; kk < 16; kk++) {
            float4 a0 = *(const float4*)&As[p][kk][tm];
            float4 a1 = *(const float4*)&As[p][kk][tm + 4];
            float4 b0 = *(const float4*)&Bs[p][kk][tn];
            float4 b1 = *(const float4*)&Bs[p][kk][tn + 4];
            float av[8] = {a0.x, a0.y, a0.z, a0.w, a1.x, a1.y, a1.z, a1.w};
            float bv[8] = {b0.x, b0.y, b0.z, b0.w, b1.x, b1.y, b1.z, b1.w};
#pragma unroll
            for (int i = 0; i < 8; i++)
#pragma unroll
                for (int j = 0; j < 8; j++) acc[i][j] += av[i] * bv[j];
        }
        if (nxt < NB) { int q = nxt & 1; stA(q); stB(q); }
        __syncthreads();
    }
    float* outp = g_xop[ks];
#pragma unroll
    for (int i = 0; i < 8; i++) {
        int row = bm + tm + i;
#pragma unroll
        for (int j = 0; j < 8; j++) {
            int n = bn + tn + j;
            if (n < GATES) outp[(size_t)row * GATES + n] = acc[i][j];
        }
    }
}

// ============ gates + state update (no smem, no block sync) ============
__global__ __launch_bounds__(384) void step_update(const float* __restrict__ rb,
                                                   const float* __restrict__ rw, int t) {
    const int b = blockIdx.x;
    const int h = threadIdx.x;
    const size_t xo = (size_t)b * GATES;
    const float* xw = g_xw + ((size_t)b * Tt + t) * GATES;

    auto colsum = [&](int col) {
        float v = xw[col] + g_xop[0][xo + col] + g_xop[1][xo + col] + g_xop[2][xo + col] + rb[col];
        if (t > 0) v += rw[(size_t)Hh * GATES + col];
        return v;
    };

    int lane = h & 31;
    float my = (lane < 6) ? colsum(lane) : 0.0f;
    float a0 = __shfl_sync(0xffffffffu, my, 0);
    float a1 = __shfl_sync(0xffffffffu, my, 1);
    float a2 = __shfl_sync(0xffffffffu, my, 2);
    float a3 = __shfl_sync(0xffffffffu, my, 3);
    float a4 = __shfl_sync(0xffffffffu, my, 4);
    float a5 = __shfl_sync(0xffffffffu, my, 5);

    float m1 = fmaxf(a0, fmaxf(a1, a2));
    float e0 = __expf(a0 - m1), e1 = __expf(a1 - m1), e2 = __expf(a2 - m1);
    float inv = 1.0f / (e0 + e1 + e2);
    float f0 = e0 * inv, f1 = (e0 + e1) * inv, f2 = (e0 + e1 + e2) * inv;

    float m2 = fmaxf(a3, fmaxf(a4, a5));
    float q0 = __expf(a3 - m2), q1 = __expf(a4 - m2), q2 = __expf(a5 - m2);
    float inv2 = 1.0f / (q0 + q1 + q2);
    float i2v = q2 * inv2, i1v = (q1 + q2) * inv2, i0v = (q0 + q1 + q2) * inv2;

    if (h == 0) g_dist[t * Bsz + b] = 1.0f - (f0 + f1 + f2) * (1.0f / 3.0f);

    int l = h >> 7;
    float F = (l == 0) ? f0 : ((l == 1) ? f1 : f2);
    float I = (l == 0) ? i0v : ((l == 1) ? i1v : i2v);

    float fg = sigf(colsum(6 + h));
    float ig = sigf(colsum(6 + Hh + h));
    float og = sigf(colsum(6 + 2 * Hh + h));
    float ci = tanhfast(colsum(6 + 3 * Hh + h));

    float c = g_c[(size_t)b * Hh + h];
    float ov = F * I;
    float cn = ov * (fg * c + ig * ci) + (F - ov) * c + (I - ov) * ci;
    g_c[(size_t)b * Hh + h] = cn;
    float hn = og * tanhfast(cn);
    g_h[(size_t)b * Hh + h] = hn;
    g_hhist[((size_t)t * Bsz + b) * Hh + h] = hn;
}

// ---------------- finalize: per-batch theme/conv/out at t = v_len-1 ----------------
#define GROUP 4
#define FIN_SMEM_FLOATS (GROUP * 3840 + GROUP * Hh + GROUP * Hh + GROUP * 64 + GROUP * Kw + GROUP * Kw + GROUP)
__global__ __launch_bounds__(384) void finalize(
    const int* __restrict__ vlen,
    const float* __restrict__ sw, const float* __restrict__ sb,
    const float* __restrict__ rsw, const float* __restrict__ rsb,
    const float* __restrict__ cw, const float* __restrict__ cb,
    const float* __restrict__ ow, const float* __restrict__ ob,
    float* __restrict__ out) {
    extern __shared__ float sm[];
    float* lh   = sm;
    float* th   = lh + GROUP * 3840;
    float* rn   = th + GROUP * Hh;
    float* s1   = rn + GROUP * Hh;
    float* ldw  = s1 + GROUP * 64;
    float* dtmp = ldw + GROUP * Kw;
    int*   tbs  = (int*)(dtmp + GROUP * Kw);

    const int tid = threadIdx.x;
    const int b0 = blockIdx.x * GROUP;

    if (tid < GROUP) tbs[tid] = vlen[b0 + tid] - 1;
    __syncthreads();
    if (tid < GROUP * Kw) {
        int g = tid / Kw, j = tid % Kw;
        int ts = tbs[g] - (Kw - 1) + j;
        dtmp[g * Kw + j] = (ts >= 0) ? g_dist[ts * Bsz + b0 + g] : 0.0f;
    }
    __syncthreads();
    if (tid < GROUP) {
        float c = 0.0f, cums[Kw];
#pragma unroll
        for (int j = 0; j < Kw; j++) { c += dtmp[tid * Kw + j]; cums[j] = c; }
        float m = cums[Kw - 1];
        float s = 0.0f, e[Kw];
#pragma unroll
        for (int j = 0; j < Kw; j++) { e[j] = __expf(cums[j] - m); s += e[j]; }
        float inv = 1.0f / s;
#pragma unroll
        for (int j = 0; j < Kw; j++) ldw[tid * Kw + j] = e[j] * inv;
    }
    __syncthreads();

    for (int g = 0; g < GROUP; g++) {
        int tb = tbs[g], b = b0 + g;
        float tr = 0.0f;
#pragma unroll
        for (int j = 0; j < Kw; j++) {
            int ts = tb - (Kw - 1) + j;
            float hv = (ts >= 0) ? g_hhist[((size_t)ts * Bsz + b) * Hh + tid] : 0.0f;
            float v = hv * ldw[g * Kw + j];
            lh[g * 3840 + j * Hh + tid] = v;
            tr += v;
        }
        th[g * Hh + tid] = tr * 0.1f;
    }
    __syncthreads();

    if (tid < GROUP * 64) {
        int g = tid >> 6, j = tid & 63;
        float a = sb[j];
        for (int h = 0; h < Hh; h++) a += th[g * Hh + h] * sw[h * 64 + j];
        s1[g * 64 + j] = fmaxf(a, 0.0f);
    }
    __syncthreads();

    float accv[GROUP];
    float cbv = cb[tid];
#pragma unroll
    for (int g = 0; g < GROUP; g++) accv[g] = cbv;
    const float2* cwp = (const float2*)(cw + (size_t)tid * (Hh * Kw));
    for (int h = 0; h < Hh; h++) {
#pragma unroll
        for (int jp = 0; jp < Kw / 2; jp++) {
            float2 w = cwp[h * (Kw / 2) + jp];
            int j0 = jp * 2;
#pragma unroll
            for (int g = 0; g < GROUP; g++) {
                accv[g] += lh[g * 3840 + j0 * Hh + h] * w.x
                         + lh[g * 3840 + (j0 + 1) * Hh + h] * w.y;
            }
        }
    }

    for (int g = 0; g < GROUP; g++) {
        float a = rsb[tid];
#pragma unroll
        for (int j = 0; j < 64; j++) a += s1[g * 64 + j] * rsw[j * Hh + tid];
        float t2 = sigf(a);
        int tb = tbs[g], b = b0 + g;
        float hf = g_hhist[((size_t)tb * Bsz + b) * Hh + tid];
        rn[g * Hh + tid] = hf + t2 * accv[g];
    }
    __syncthreads();

    if (tid < GROUP * LAB) {
        int g = tid / LAB, lab = tid % LAB;
        float a = ob[lab];
        for (int h = 0; h < Hh; h++) a += rn[g * Hh + h] * ow[h * LAB + lab];
        out[(b0 + g) * LAB + lab] = a;
    }
}

// ---------------- launch ----------------
extern "C" void kernel_launch(void* const* d_in, const int* in_sizes, int n_in,
                              void* d_out, int out_size) {
    const float* X   = (const float*)d_in[0];
    const int*   vlen= (const int*)  d_in[1];
    const float* kw  = (const float*)d_in[2];
    const float* kb  = (const float*)d_in[3];
    const float* rw  = (const float*)d_in[4];
    const float* rb  = (const float*)d_in[5];
    const float* sw  = (const float*)d_in[6];
    const float* sb  = (const float*)d_in[7];
    const float* rsw = (const float*)d_in[8];
    const float* rsb = (const float*)d_in[9];
    const float* cw  = (const float*)d_in[10];
    const float* cb  = (const float*)d_in[11];
    const float* ow  = (const float*)d_in[12];
    const float* ob  = (const float*)d_in[13];
    float* out = (float*)d_out;

    cudaFuncSetAttribute(finalize, cudaFuncAttributeMaxDynamicSharedMemorySize,
                         FIN_SMEM_FLOATS * (int)sizeof(float));

    init_state<<<48, 512>>>();
    gemm_xw<<<dim3((GATES + 127) / 128, (Bsz * Tt) / 128), 256>>>(X, kw, kb);
    for (int t = 0; t < Tt; t++) {
        gemm_rec<<<dim3((GATES + 127) / 128, Bsz / 128, 3), 256>>>(rw);
        step_update<<<Bsz, Hh>>>(rb, rw, t);
    }
    finalize<<<Bsz / GROUP, Hh, FIN_SMEM_FLOATS * (int)sizeof(float)>>>(
        vlen, sw, sb, rsw, rsb, cw, cb, ow, ob, out);
}